// round 6
// baseline (speedup 1.0000x reference)
#include <cuda_runtime.h>
#include <cuda_fp16.h>

// ROIAlign(7x7, sr=2) + global avg pool, separable-weight formulation.
// out[roi,ch] = sum_r a[r] * sum_c b[c] * F[bi,ch,r,c]; a/b are the y/x
// bilinear weight marginals (b pre-scaled by 1/196).
//
// R5: widen channel interleave to 8 (2 groups of 8 channels per warp).
// Each row iteration issues 8 independent LDG.128 from one base pointer
// with constant 512KB-step offsets -> ~16 loads in flight per warp,
// driving L2 toward saturation; loop + reduction overhead halves.

#define NTHREADS 256
#define NWARPS   8
#define C_CH     256
#define HW       128
#define CH_STRIDE_B (HW * HW * 4)            // 64 KB per channel

__global__ __launch_bounds__(NTHREADS)
void roi_align_pool_kernel(const float* __restrict__ feat,
                           const float* __restrict__ rois,
                           float* __restrict__ out,
                           int n_rois)
{
    __shared__ float  a_sh[HW];        // row (H) weights
    __shared__ float  b_sh[192];       // col (W) weights (x 1/196), zero-padded
    __shared__ float2 rows_sh[64];     // compacted (weight, byte-offset)
    __shared__ int rlo_s, rhi_s, clo_s, chi_s, bi_s, nr_s;

    const int roi = blockIdx.x;
    const int tid = threadIdx.x;

    if (tid == 0) {
        rlo_s = 1 << 30; rhi_s = -1;
        clo_s = 1 << 30; chi_s = -1;
        bi_s = (int)rois[roi * 6 + 0];
        if (blockIdx.y == 0)  // second output: gt = rois[:,1]
            out[(size_t)n_rois * C_CH + roi] = rois[roi * 6 + 1];
    }
    if (tid < 192) {
        if (tid < HW) a_sh[tid] = 0.f;
        b_sh[tid] = 0.f;
    }
    __syncthreads();

    // One warp builds the separable weight vectors.
    if (tid < 32) {
        const bool isY = (tid < 14);
        const bool isX = (tid >= 16 && tid < 30);
        if (isY || isX) {
            const int s = isY ? tid : tid - 16;
            const float cx = rois[roi * 6 + 2];
            const float cy = rois[roi * 6 + 3];
            const float w  = rois[roi * 6 + 4];
            const float h  = rois[roi * 6 + 5];
            // Reference rounds the scaled corners through fp16.
            const float x1 = __half2float(__float2half_rn((cx - 0.5f * w) * 128.f));
            const float x2 = __half2float(__float2half_rn((cx + 0.5f * w) * 128.f));
            const float y1 = __half2float(__float2half_rn((cy - 0.5f * h) * 128.f));
            const float y2 = __half2float(__float2half_rn((cy + 0.5f * h) * 128.f));
            const float rw = fmaxf(x2 - x1, 1.f);
            const float rh = fmaxf(y2 - y1, 1.f);

            const float off   = 0.25f + 0.5f * (float)s;   // p + (sub+0.5)/2
            const float start = isY ? y1 : x1;
            const float ext   = isY ? rh : rw;
            const float coord = start + off * (ext / 7.f);

            if (coord > -1.f && coord < 128.f) {
                const float cl = fminf(fmaxf(coord, 0.f), 127.f);
                const int   i0 = (int)floorf(cl);
                const int   i1 = min(i0 + 1, HW - 1);
                const float l  = cl - (float)i0;
                const float hi = 1.f - l;
                if (isY) {
                    atomicAdd(&a_sh[i0], hi);
                    atomicAdd(&a_sh[i1], l);
                    atomicMin(&rlo_s, i0);
                    atomicMax(&rhi_s, i1);
                } else {
                    const float inv = 1.f / 196.f;  // fold in the mean
                    atomicAdd(&b_sh[i0], hi * inv);
                    atomicAdd(&b_sh[i1], l * inv);
                    atomicMin(&clo_s, i0);
                    atomicMax(&chi_s, i1);
                }
            }
        }
    }
    __syncthreads();

    // Compact nonzero rows (weight + precomputed byte offset).
    if (tid == 0) {
        int n = 0;
        if (rhi_s >= rlo_s && chi_s >= clo_s) {
            for (int r = rlo_s; r <= rhi_s; ++r) {
                const float w = a_sh[r];
                if (w != 0.f)
                    rows_sh[n++] = make_float2(w, __int_as_float(r * HW * 4));
            }
        }
        nr_s = n;
    }
    __syncthreads();

    const int nr  = nr_s;
    const int clo = clo_s, chi = chi_s;
    const int warp = tid >> 5;
    const int lane = tid & 31;

    // Column-chunk geometry (pow2 number of float4 chunks, <= 16).
    int base = 0, ncp = 1;
    if (chi >= clo) {
        base = clo & ~3;
        const int nchunks = ((chi - base) >> 2) + 1;
        ncp = (nchunks <= 1) ? 1 : (1 << (32 - __clz(nchunks - 1)));
    }
    const int logn   = 31 - __clz(ncp);
    const int rpi    = 32 >> logn;              // rows per iteration
    const int cchunk = lane & (ncp - 1);
    const int rsub   = lane >> logn;

    const int colv = base + 4 * cchunk;
    const float4 bw = *(const float4*)&b_sh[colv];   // zero beyond chi (padded)
    const int loadcol = min(colv, HW - 4);           // clamp: weight is 0 there

    const char* fb = (const char*)(feat + (size_t)bi_s * C_CH * (HW * HW));
    const int chBase = blockIdx.y * (C_CH / 2);
    const int c0 = chBase + warp;     // warp's channels: c0 + 8*j, j=0..15

    #pragma unroll
    for (int kout = 0; kout < 2; ++kout) {
        // group channels: c0 + 64*kout + 8*k, k=0..7 (constant 512KB apart)
        const char* gp = fb + ((size_t)(c0 + 64 * kout) * (HW * HW) + loadcol) * 4;
        float a0 = 0.f, a1 = 0.f, a2 = 0.f, a3 = 0.f;
        float a4 = 0.f, a5 = 0.f, a6 = 0.f, a7 = 0.f;
        #pragma unroll 1
        for (int i = rsub; i < nr; i += rpi) {
            const float2 rw2 = rows_sh[i];
            const char* p = gp + __float_as_int(rw2.y);
            const float4 f0 = *(const float4*)(p);
            const float4 f1 = *(const float4*)(p + 8 * CH_STRIDE_B);
            const float4 f2 = *(const float4*)(p + 16 * CH_STRIDE_B);
            const float4 f3 = *(const float4*)(p + 24 * CH_STRIDE_B);
            const float4 f4 = *(const float4*)(p + 32 * CH_STRIDE_B);
            const float4 f5 = *(const float4*)(p + 40 * CH_STRIDE_B);
            const float4 f6 = *(const float4*)(p + 48 * CH_STRIDE_B);
            const float4 f7 = *(const float4*)(p + 56 * CH_STRIDE_B);
            float s0 = bw.x * f0.x; s0 = fmaf(bw.y, f0.y, s0);
            s0 = fmaf(bw.z, f0.z, s0); s0 = fmaf(bw.w, f0.w, s0);
            float s1 = bw.x * f1.x; s1 = fmaf(bw.y, f1.y, s1);
            s1 = fmaf(bw.z, f1.z, s1); s1 = fmaf(bw.w, f1.w, s1);
            float s2 = bw.x * f2.x; s2 = fmaf(bw.y, f2.y, s2);
            s2 = fmaf(bw.z, f2.z, s2); s2 = fmaf(bw.w, f2.w, s2);
            float s3 = bw.x * f3.x; s3 = fmaf(bw.y, f3.y, s3);
            s3 = fmaf(bw.z, f3.z, s3); s3 = fmaf(bw.w, f3.w, s3);
            float s4 = bw.x * f4.x; s4 = fmaf(bw.y, f4.y, s4);
            s4 = fmaf(bw.z, f4.z, s4); s4 = fmaf(bw.w, f4.w, s4);
            float s5 = bw.x * f5.x; s5 = fmaf(bw.y, f5.y, s5);
            s5 = fmaf(bw.z, f5.z, s5); s5 = fmaf(bw.w, f5.w, s5);
            float s6 = bw.x * f6.x; s6 = fmaf(bw.y, f6.y, s6);
            s6 = fmaf(bw.z, f6.z, s6); s6 = fmaf(bw.w, f6.w, s6);
            float s7 = bw.x * f7.x; s7 = fmaf(bw.y, f7.y, s7);
            s7 = fmaf(bw.z, f7.z, s7); s7 = fmaf(bw.w, f7.w, s7);
            a0 = fmaf(rw2.x, s0, a0);
            a1 = fmaf(rw2.x, s1, a1);
            a2 = fmaf(rw2.x, s2, a2);
            a3 = fmaf(rw2.x, s3, a3);
            a4 = fmaf(rw2.x, s4, a4);
            a5 = fmaf(rw2.x, s5, a5);
            a6 = fmaf(rw2.x, s6, a6);
            a7 = fmaf(rw2.x, s7, a7);
        }
        // eight independent butterfly reductions (pipelined)
        #pragma unroll
        for (int o = 16; o; o >>= 1) {
            a0 += __shfl_xor_sync(0xffffffffu, a0, o);
            a1 += __shfl_xor_sync(0xffffffffu, a1, o);
            a2 += __shfl_xor_sync(0xffffffffu, a2, o);
            a3 += __shfl_xor_sync(0xffffffffu, a3, o);
            a4 += __shfl_xor_sync(0xffffffffu, a4, o);
            a5 += __shfl_xor_sync(0xffffffffu, a5, o);
            a6 += __shfl_xor_sync(0xffffffffu, a6, o);
            a7 += __shfl_xor_sync(0xffffffffu, a7, o);
        }
        if (lane == 0) {
            float* op = out + (size_t)roi * C_CH + c0 + 64 * kout;
            op[0]  = a0;
            op[8]  = a1;
            op[16] = a2;
            op[24] = a3;
            op[32] = a4;
            op[40] = a5;
            op[48] = a6;
            op[56] = a7;
        }
    }
}

extern "C" void kernel_launch(void* const* d_in, const int* in_sizes, int n_in,
                              void* d_out, int out_size)
{
    const float* feat = (const float*)d_in[0];   // (4, 256, 128, 128) fp32
    const float* rois = (const float*)d_in[1];   // (N, 6) fp32
    float* out = (float*)d_out;

    const int n_rois = in_sizes[1] / 6;          // 512
    (void)n_in; (void)out_size;

    dim3 grid(n_rois, 2);
    roi_align_pool_kernel<<<grid, NTHREADS>>>(feat, rois, out, n_rois);
}

// round 7
// speedup vs baseline: 1.0659x; 1.0659x over previous
#include <cuda_runtime.h>
#include <cuda_fp16.h>

// ROIAlign(7x7, sr=2) + global avg pool, separable-weight formulation.
// out[roi,ch] = sum_r a[r] * sum_c b[c] * F[bi,ch,r,c]; a/b are the y/x
// bilinear weight marginals (b pre-scaled by 1/196).
//
// R6: exact-cover flat work list. Setup flattens (nonzero rows x column
// chunks) into T shared entries {row weight, byte offset} + per-chunk
// float4 column weights. Lanes stride the list (t += 32): no idle lanes,
// no pow2 over-fetch. Each warp owns 8 channels (8 independent LDG.128
// per iteration, 512KB constant strides); launch_bounds(256,3) unlocks
// enough registers to keep them in flight. Grid = 512 rois x 4 ch-quarters.

#define NTHREADS 256
#define NWARPS   8
#define C_CH     256
#define HW       128
#define CH_STRIDE_B (HW * HW * 4)            // 64 KB per channel
#define MAX_T    400                          // >= 28 rows * 14 chunks

__global__ __launch_bounds__(NTHREADS, 3)
void roi_align_pool_kernel(const float* __restrict__ feat,
                           const float* __restrict__ rois,
                           float* __restrict__ out,
                           int n_rois)
{
    __shared__ float  a_sh[HW];        // row (H) weights
    __shared__ float  b_sh[192];       // col (W) weights (x 1/196), zero-padded
    __shared__ float2 rows_sh[64];     // compacted (weight, row byte-offset)
    __shared__ float2 wo_sh[MAX_T];    // flat: (row weight, full byte-offset)
    __shared__ float4 bwt_sh[MAX_T];   // flat: column-weight float4 per entry
    __shared__ int rlo_s, rhi_s, clo_s, chi_s, bi_s, nr_s, T_s, base_s, nch_s;

    const int roi = blockIdx.x;
    const int tid = threadIdx.x;

    if (tid == 0) {
        rlo_s = 1 << 30; rhi_s = -1;
        clo_s = 1 << 30; chi_s = -1;
        bi_s = (int)rois[roi * 6 + 0];
        if (blockIdx.y == 0)  // second output: gt = rois[:,1]
            out[(size_t)n_rois * C_CH + roi] = rois[roi * 6 + 1];
    }
    if (tid < 192) {
        if (tid < HW) a_sh[tid] = 0.f;
        b_sh[tid] = 0.f;
    }
    __syncthreads();

    // One warp builds the separable weight vectors.
    if (tid < 32) {
        const bool isY = (tid < 14);
        const bool isX = (tid >= 16 && tid < 30);
        if (isY || isX) {
            const int s = isY ? tid : tid - 16;
            const float cx = rois[roi * 6 + 2];
            const float cy = rois[roi * 6 + 3];
            const float w  = rois[roi * 6 + 4];
            const float h  = rois[roi * 6 + 5];
            // Reference rounds the scaled corners through fp16.
            const float x1 = __half2float(__float2half_rn((cx - 0.5f * w) * 128.f));
            const float x2 = __half2float(__float2half_rn((cx + 0.5f * w) * 128.f));
            const float y1 = __half2float(__float2half_rn((cy - 0.5f * h) * 128.f));
            const float y2 = __half2float(__float2half_rn((cy + 0.5f * h) * 128.f));
            const float rw = fmaxf(x2 - x1, 1.f);
            const float rh = fmaxf(y2 - y1, 1.f);

            const float off   = 0.25f + 0.5f * (float)s;   // p + (sub+0.5)/2
            const float start = isY ? y1 : x1;
            const float ext   = isY ? rh : rw;
            const float coord = start + off * (ext / 7.f);

            if (coord > -1.f && coord < 128.f) {
                const float cl = fminf(fmaxf(coord, 0.f), 127.f);
                const int   i0 = (int)floorf(cl);
                const int   i1 = min(i0 + 1, HW - 1);
                const float l  = cl - (float)i0;
                const float hi = 1.f - l;
                if (isY) {
                    atomicAdd(&a_sh[i0], hi);
                    atomicAdd(&a_sh[i1], l);
                    atomicMin(&rlo_s, i0);
                    atomicMax(&rhi_s, i1);
                } else {
                    const float inv = 1.f / 196.f;  // fold in the mean
                    atomicAdd(&b_sh[i0], hi * inv);
                    atomicAdd(&b_sh[i1], l * inv);
                    atomicMin(&clo_s, i0);
                    atomicMax(&chi_s, i1);
                }
            }
        }
    }
    __syncthreads();

    // Compact nonzero rows; compute flat-list geometry.
    if (tid == 0) {
        int n = 0;
        int base = 0, nch = 0;
        if (rhi_s >= rlo_s && chi_s >= clo_s) {
            for (int r = rlo_s; r <= rhi_s; ++r) {
                const float w = a_sh[r];
                if (w != 0.f)
                    rows_sh[n++] = make_float2(w, __int_as_float(r * HW * 4));
            }
            base = clo_s & ~3;
            nch  = ((chi_s - base) >> 2) + 1;   // exact chunk count (<=14)
        }
        nr_s = n; base_s = base; nch_s = nch;
        T_s = n * nch;
    }
    __syncthreads();

    // Build the flat work list in parallel.
    const int T = T_s;
    {
        const int base = base_s, nch = nch_s;
        for (int t = tid; t < T; t += NTHREADS) {
            const int row = t / nch;
            const int c   = t - row * nch;
            const float2 rr = rows_sh[row];
            wo_sh[t] = make_float2(
                rr.x, __int_as_float(__float_as_int(rr.y) + base * 4 + 16 * c));
            bwt_sh[t] = *(const float4*)&b_sh[base + 4 * c];
        }
    }
    __syncthreads();

    const int warp = tid >> 5;
    const int lane = tid & 31;

    const char* fb = (const char*)(feat + (size_t)bi_s * C_CH * (HW * HW));
    const int c0 = blockIdx.y * 64 + warp;    // warp's channels: c0 + 8k, k=0..7
    const char* cb = fb + (size_t)c0 * CH_STRIDE_B;

    float a0 = 0.f, a1 = 0.f, a2 = 0.f, a3 = 0.f;
    float a4 = 0.f, a5 = 0.f, a6 = 0.f, a7 = 0.f;
    #pragma unroll 1
    for (int t = lane; t < T; t += 32) {
        const float2 m  = wo_sh[t];
        const float4 bw = bwt_sh[t];
        const char* p = cb + __float_as_int(m.y);
        const float4 f0 = *(const float4*)(p);
        const float4 f1 = *(const float4*)(p + 8  * CH_STRIDE_B);
        const float4 f2 = *(const float4*)(p + 16 * CH_STRIDE_B);
        const float4 f3 = *(const float4*)(p + 24 * CH_STRIDE_B);
        const float4 f4 = *(const float4*)(p + 32 * CH_STRIDE_B);
        const float4 f5 = *(const float4*)(p + 40 * CH_STRIDE_B);
        const float4 f6 = *(const float4*)(p + 48 * CH_STRIDE_B);
        const float4 f7 = *(const float4*)(p + 56 * CH_STRIDE_B);
        float s0 = bw.x * f0.x; s0 = fmaf(bw.y, f0.y, s0);
        s0 = fmaf(bw.z, f0.z, s0); s0 = fmaf(bw.w, f0.w, s0);
        float s1 = bw.x * f1.x; s1 = fmaf(bw.y, f1.y, s1);
        s1 = fmaf(bw.z, f1.z, s1); s1 = fmaf(bw.w, f1.w, s1);
        float s2 = bw.x * f2.x; s2 = fmaf(bw.y, f2.y, s2);
        s2 = fmaf(bw.z, f2.z, s2); s2 = fmaf(bw.w, f2.w, s2);
        float s3 = bw.x * f3.x; s3 = fmaf(bw.y, f3.y, s3);
        s3 = fmaf(bw.z, f3.z, s3); s3 = fmaf(bw.w, f3.w, s3);
        float s4 = bw.x * f4.x; s4 = fmaf(bw.y, f4.y, s4);
        s4 = fmaf(bw.z, f4.z, s4); s4 = fmaf(bw.w, f4.w, s4);
        float s5 = bw.x * f5.x; s5 = fmaf(bw.y, f5.y, s5);
        s5 = fmaf(bw.z, f5.z, s5); s5 = fmaf(bw.w, f5.w, s5);
        float s6 = bw.x * f6.x; s6 = fmaf(bw.y, f6.y, s6);
        s6 = fmaf(bw.z, f6.z, s6); s6 = fmaf(bw.w, f6.w, s6);
        float s7 = bw.x * f7.x; s7 = fmaf(bw.y, f7.y, s7);
        s7 = fmaf(bw.z, f7.z, s7); s7 = fmaf(bw.w, f7.w, s7);
        a0 = fmaf(m.x, s0, a0);
        a1 = fmaf(m.x, s1, a1);
        a2 = fmaf(m.x, s2, a2);
        a3 = fmaf(m.x, s3, a3);
        a4 = fmaf(m.x, s4, a4);
        a5 = fmaf(m.x, s5, a5);
        a6 = fmaf(m.x, s6, a6);
        a7 = fmaf(m.x, s7, a7);
    }

    // eight independent butterfly reductions (pipelined)
    #pragma unroll
    for (int o = 16; o; o >>= 1) {
        a0 += __shfl_xor_sync(0xffffffffu, a0, o);
        a1 += __shfl_xor_sync(0xffffffffu, a1, o);
        a2 += __shfl_xor_sync(0xffffffffu, a2, o);
        a3 += __shfl_xor_sync(0xffffffffu, a3, o);
        a4 += __shfl_xor_sync(0xffffffffu, a4, o);
        a5 += __shfl_xor_sync(0xffffffffu, a5, o);
        a6 += __shfl_xor_sync(0xffffffffu, a6, o);
        a7 += __shfl_xor_sync(0xffffffffu, a7, o);
    }
    if (lane == 0) {
        float* op = out + (size_t)roi * C_CH + c0;
        op[0]  = a0;
        op[8]  = a1;
        op[16] = a2;
        op[24] = a3;
        op[32] = a4;
        op[40] = a5;
        op[48] = a6;
        op[56] = a7;
    }
}

extern "C" void kernel_launch(void* const* d_in, const int* in_sizes, int n_in,
                              void* d_out, int out_size)
{
    const float* feat = (const float*)d_in[0];   // (4, 256, 128, 128) fp32
    const float* rois = (const float*)d_in[1];   // (N, 6) fp32
    float* out = (float*)d_out;

    const int n_rois = in_sizes[1] / 6;          // 512
    (void)n_in; (void)out_size;

    dim3 grid(n_rois, 4);
    roi_align_pool_kernel<<<grid, NTHREADS>>>(feat, rois, out, n_rois);
}